// round 6
// baseline (speedup 1.0000x reference)
#include <cuda_runtime.h>
#include <math.h>

#define N_NODES 4096
#define NFEAT   128
#define NHID    128
#define NHEADS  4
#define NCLASS  32
#define KEDGE   32
#define ALPHA_LRELU 0.2f

// ---------------- scratch ----------------
__device__ float g_h  [N_NODES * NHEADS * NHID];   // [n][head*128+d]
__device__ float g_xc [N_NODES * NHEADS * NHID];
__device__ float g_f1 [NHEADS * N_NODES];
__device__ float g_f2 [NHEADS * N_NODES];
__device__ int2  g_wj [N_NODES * NHEADS * KEDGE];  // {w_bits, j*32}, w=0 padded
__device__ float g_h2 [N_NODES * NCLASS];
__device__ float g_f1o[N_NODES];
__device__ float g_f2o[N_NODES];

// ---------------- K1: h = x @ Ws  (32m x 128n tiles, fused f1/f2) ----------------
// grid (4 heads, 128 row-tiles), block 256
__global__ void k_gemm1(const float* __restrict__ X, const float* __restrict__ Ws,
                        const float* __restrict__ a) {
    __shared__ __align__(16) float As[32][36];    // [m][k]
    __shared__ __align__(16) float Bs[32][128];   // [k][n]
    int head = blockIdx.x;
    int m0   = blockIdx.y * 32;
    const float* B = Ws + head * NFEAT * NHID;
    int tid  = threadIdx.x;
    int tx   = tid & 31;
    int ty   = tid >> 5;

    int ar  = tid >> 3, ac4 = (tid & 7) * 4;
    int bk  = tid >> 5, bn4 = (tid & 31) * 4;

    float acc[4][4] = {};
    for (int kc = 0; kc < NFEAT; kc += 32) {
        *(float4*)&As[ar][ac4] = *(const float4*)&X[(m0 + ar) * NFEAT + kc + ac4];
        #pragma unroll
        for (int t = 0; t < 4; t++)
            *(float4*)&Bs[bk + t * 8][bn4] = *(const float4*)&B[(kc + bk + t * 8) * NHID + bn4];
        __syncthreads();
        #pragma unroll
        for (int kk = 0; kk < 32; kk++) {
            float av[4];
            #pragma unroll
            for (int i = 0; i < 4; i++) av[i] = As[ty * 4 + i][kk];
            float4 b4 = *(float4*)&Bs[kk][tx * 4];
            float bv[4] = {b4.x, b4.y, b4.z, b4.w};
            #pragma unroll
            for (int i = 0; i < 4; i++)
                #pragma unroll
                for (int j = 0; j < 4; j++)
                    acc[i][j] += av[i] * bv[j];
        }
        __syncthreads();
    }
    float a1j[4], a2j[4];
    #pragma unroll
    for (int j = 0; j < 4; j++) {
        a1j[j] = a[head * 256 + tx * 4 + j];
        a2j[j] = a[head * 256 + 128 + tx * 4 + j];
    }
    #pragma unroll
    for (int i = 0; i < 4; i++) {
        int row = m0 + ty * 4 + i;
        *(float4*)&g_h[(size_t)row * 512 + head * 128 + tx * 4] =
            make_float4(acc[i][0], acc[i][1], acc[i][2], acc[i][3]);
        float s1 = 0.f, s2 = 0.f;
        #pragma unroll
        for (int j = 0; j < 4; j++) { s1 += acc[i][j] * a1j[j]; s2 += acc[i][j] * a2j[j]; }
        #pragma unroll
        for (int o = 16; o; o >>= 1) {
            s1 += __shfl_xor_sync(0xffffffffu, s1, o);
            s2 += __shfl_xor_sync(0xffffffffu, s2, o);
        }
        if (tx == 0) {
            g_f1[head * N_NODES + row] = s1;
            g_f2[head * N_NODES + row] = s2;
        }
    }
}

// ---------------- K2: softmax weights, inline dedup, packed {w, j*32} ----------------
__global__ void k_wgt(const int* __restrict__ edge) {
    int tid  = threadIdx.x;
    int row  = blockIdx.x * 4 + (tid >> 7);
    int head = (tid >> 5) & 3;
    int lane = tid & 31;
    int base = row & ~1023;

    int e = edge[row * KEDGE + lane];
    bool valid = (e >= 0);
    unsigned key = valid ? (unsigned)e : (0x40000000u + (unsigned)lane);
    unsigned grp = __match_any_sync(0xffffffffu, key);
    bool uniq = valid && ((__ffs(grp) - 1) == lane);

    float p = 0.f;
    if (uniq) {
        float t = g_f1[head * N_NODES + row] + g_f2[head * N_NODES + base + e];
        float la = (t > 0.f) ? t : ALPHA_LRELU * t;
        p = __expf(la);
    }
    float s = p;
    #pragma unroll
    for (int o = 16; o; o >>= 1) s += __shfl_xor_sync(0xffffffffu, s, o);
    int2 v;
    v.x = __float_as_int(p / s);
    v.y = (valid ? e : 0) * 32;
    g_wj[(row * 4 + head) * KEDGE + lane] = v;
}

// ---------------- K3: layer-1 aggregation, smem tile, int4 wj loads ----------------
// grid (dchunk=4, head=4, part*2+half=8), block 1024, dyn smem 128KB
__global__ void k_attn1_agg() {
    extern __shared__ __align__(16) float tile[];   // [1024 nbrs][32 d]
    int dc   = blockIdx.x;
    int head = blockIdx.y;
    int part = blockIdx.z >> 1;
    int half = blockIdx.z & 1;
    int base = part << 10;
    int tid  = threadIdx.x;

    const float* src = g_h + (size_t)base * 512 + head * 128 + dc * 32;
    #pragma unroll
    for (int i = tid; i < 1024 * 8; i += 1024) {
        int j = i >> 3, d4 = i & 7;
        *(float4*)&tile[j * 32 + d4 * 4] = *(const float4*)&src[(size_t)j * 512 + d4 * 4];
    }
    __syncthreads();

    int lane = tid & 31, warp = tid >> 5;
    int row0 = base + half * 512 + warp * 16;
    const float* tl = tile + lane;
    #pragma unroll 1
    for (int r = 0; r < 16; r += 2) {
        int rowA = row0 + r, rowB = row0 + r + 1;
        const int4* wjA = (const int4*)(g_wj + (rowA * 4 + head) * KEDGE);
        const int4* wjB = (const int4*)(g_wj + (rowB * 4 + head) * KEDGE);
        float aA = 0.f, aB = 0.f;
        #pragma unroll
        for (int k = 0; k < 16; k++) {
            int4 pA = wjA[k];
            int4 pB = wjB[k];
            aA += __int_as_float(pA.x) * tl[pA.y];
            aA += __int_as_float(pA.z) * tl[pA.w];
            aB += __int_as_float(pB.x) * tl[pB.y];
            aB += __int_as_float(pB.z) * tl[pB.w];
        }
        float oA = aA > 0.f ? aA : expm1f(aA);
        float oB = aB > 0.f ? aB : expm1f(aB);
        g_xc[(size_t)rowA * 512 + head * 128 + dc * 32 + lane] = oA;
        g_xc[(size_t)rowB * 512 + head * 128 + dc * 32 + lane] = oB;
    }
}

// ---------------- K4: h2 = xc @ W_out — NO smem, W stays L1-resident ----------------
// grid 512, block 128 (4 warps), warp = 2 rows, lane = class
__global__ void k_gemm2(const float* __restrict__ W, const float* __restrict__ a_out) {
    int tid  = threadIdx.x;
    int lane = tid & 31, warp = tid >> 5;
    int row  = (blockIdx.x * 4 + warp) * 2;
    const float4* x0 = (const float4*)(g_xc + (size_t)row * 512);
    const float4* x1 = x0 + 128;
    const float*  Wl = W + lane;

    float acc0 = 0.f, acc1 = 0.f;
    #pragma unroll 8
    for (int q = 0; q < 128; q++) {
        float4 v0 = x0[q];                     // uniform LDG.128
        float4 v1 = x1[q];
        const float* wp = Wl + q * 128;        // 4 coalesced 128B lines (L1 hit)
        float w0 = wp[0], w1 = wp[32], w2 = wp[64], w3 = wp[96];
        acc0 += v0.x * w0 + v0.y * w1 + v0.z * w2 + v0.w * w3;
        acc1 += v1.x * w0 + v1.y * w1 + v1.z * w2 + v1.w * w3;
    }
    g_h2[row * 32 + lane]       = acc0;
    g_h2[(row + 1) * 32 + lane] = acc1;

    float a1 = a_out[lane], a2 = a_out[32 + lane];
    float s1 = acc0 * a1, s2 = acc0 * a2, s3 = acc1 * a1, s4 = acc1 * a2;
    #pragma unroll
    for (int o = 16; o; o >>= 1) {
        s1 += __shfl_xor_sync(0xffffffffu, s1, o);
        s2 += __shfl_xor_sync(0xffffffffu, s2, o);
        s3 += __shfl_xor_sync(0xffffffffu, s3, o);
        s4 += __shfl_xor_sync(0xffffffffu, s4, o);
    }
    if (lane == 0) {
        g_f1o[row]     = s1;  g_f2o[row]     = s2;
        g_f1o[row + 1] = s3;  g_f2o[row + 1] = s4;
    }
}

// ---------------- K5: layer-2 attention + elu + log_softmax ----------------
__global__ void k_attn2(const int* __restrict__ edge, float* __restrict__ out) {
    int row  = blockIdx.x * 4 + (threadIdx.x >> 5);
    int lane = threadIdx.x & 31;
    int base = row & ~1023;

    int e = edge[row * KEDGE + lane];
    bool valid = (e >= 0);
    unsigned key = valid ? (unsigned)e : (0x40000000u + (unsigned)lane);
    unsigned grp = __match_any_sync(0xffffffffu, key);
    bool uniq = valid && ((__ffs(grp) - 1) == lane);

    float p = 0.f;
    if (uniq) {
        float t = g_f1o[row] + g_f2o[base + e];
        float la = (t > 0.f) ? t : ALPHA_LRELU * t;
        p = __expf(la);
    }
    float s = p;
    #pragma unroll
    for (int o = 16; o; o >>= 1) s += __shfl_xor_sync(0xffffffffu, s, o);
    float wgt = p / s;
    int j = valid ? e : 0;

    float acc = 0.f;
    #pragma unroll 8
    for (int k = 0; k < KEDGE; k++) {
        float wk = __shfl_sync(0xffffffffu, wgt, k);
        int   jk = __shfl_sync(0xffffffffu, j, k);
        acc += wk * g_h2[(base + jk) * 32 + lane];
    }
    float v = acc > 0.f ? acc : expm1f(acc);
    float m2 = v;
    #pragma unroll
    for (int o = 16; o; o >>= 1) m2 = fmaxf(m2, __shfl_xor_sync(0xffffffffu, m2, o));
    float se = __expf(v - m2);
    #pragma unroll
    for (int o = 16; o; o >>= 1) se += __shfl_xor_sync(0xffffffffu, se, o);
    out[row * 32 + lane] = v - m2 - logf(se);
}

// ---------------- launch ----------------
extern "C" void kernel_launch(void* const* d_in, const int* in_sizes, int n_in,
                              void* d_out, int out_size) {
    const float* x     = (const float*)d_in[0];
    const int*   edge  = (const int*)d_in[1];
    const float* Ws    = (const float*)d_in[3];
    const float* a     = (const float*)d_in[4];
    const float* W_out = (const float*)d_in[5];
    const float* a_out = (const float*)d_in[6];
    float* out = (float*)d_out;

    cudaFuncSetAttribute(k_attn1_agg, cudaFuncAttributeMaxDynamicSharedMemorySize,
                         1024 * 32 * sizeof(float));

    dim3 g1(4, 128);
    k_gemm1<<<g1, 256>>>(x, Ws, a);
    k_wgt<<<N_NODES / 4, 512>>>(edge);
    dim3 ga(4, 4, 8);
    k_attn1_agg<<<ga, 1024, 1024 * 32 * sizeof(float)>>>();
    k_gemm2<<<512, 128>>>(W_out, a_out);
    k_attn2<<<N_NODES / 4, 128>>>(edge, out);
}

// round 7
// speedup vs baseline: 1.0609x; 1.0609x over previous
#include <cuda_runtime.h>
#include <math.h>

#define N_NODES 4096
#define NFEAT   128
#define NHID    128
#define NHEADS  4
#define NCLASS  32
#define KEDGE   32
#define ALPHA_LRELU 0.2f

// ---------------- scratch (no allocations allowed) ----------------
__device__ float g_h  [N_NODES * NHEADS * NHID];   // [n][head*128+d]
__device__ float g_xc [N_NODES * NHEADS * NHID];   // [n][head*128+d]
__device__ float g_f1 [NHEADS * N_NODES];
__device__ float g_f2 [NHEADS * N_NODES];
__device__ float g_h2 [N_NODES * NCLASS];
__device__ float g_f1o[N_NODES];
__device__ float g_f2o[N_NODES];
__device__ int   g_cnt[N_NODES];
__device__ int   g_nbr[N_NODES * KEDGE];

// ---------------- K1: dedup neighbor lists ----------------
__global__ void k_nbrs(const int* __restrict__ edge) {
    int row  = blockIdx.x * 4 + (threadIdx.x >> 5);
    int lane = threadIdx.x & 31;
    int e = edge[row * KEDGE + lane];
    bool valid = (e >= 0);
    unsigned key = valid ? (unsigned)e : (0x40000000u + (unsigned)lane);
    unsigned grp = __match_any_sync(0xffffffffu, key);
    bool uniq = valid && ((__ffs(grp) - 1) == lane);
    unsigned bal = __ballot_sync(0xffffffffu, uniq);
    if (uniq) {
        int pos = __popc(bal & ((1u << lane) - 1u));
        g_nbr[row * KEDGE + pos] = e;   // local index within 1024-block
    }
    if (lane == 0) g_cnt[row] = __popc(bal);
}

// ---------------- K2: h = x @ concat(Ws) ----------------
// C[4096 x 512], A = x [4096 x 128], B per head = Ws[h] [128 x 128]
__global__ void k_gemm1(const float* __restrict__ X, const float* __restrict__ Ws) {
    __shared__ float As[64][65];  // [k][m]
    __shared__ float Bs[64][65];  // [k][n]
    int bx = blockIdx.x;          // 0..7  (64-col tiles of 512)
    int by = blockIdx.y;          // 0..63 (64-row tiles of 4096)
    int n0 = bx * 64;
    int head = n0 >> 7;
    int nloc = n0 & 127;
    const float* B = Ws + head * NFEAT * NHID;
    int m0 = by * 64;
    int tid = threadIdx.x;
    int tx = tid & 15, ty = tid >> 4;

    float acc[4][4] = {};
    for (int kc = 0; kc < NFEAT; kc += 64) {
        #pragma unroll
        for (int t = 0; t < 16; t++) {
            int e = t * 256 + tid;
            { int k = e & 63, m = e >> 6;      // A: coalesced over k
              As[k][m] = X[(m0 + m) * NFEAT + kc + k]; }
            { int n = e & 63, k = e >> 6;      // B: coalesced over n
              Bs[k][n] = B[(kc + k) * NHID + nloc + n]; }
        }
        __syncthreads();
        #pragma unroll 16
        for (int kk = 0; kk < 64; kk++) {
            float av[4], bv[4];
            #pragma unroll
            for (int i = 0; i < 4; i++) av[i] = As[kk][ty * 4 + i];
            #pragma unroll
            for (int j = 0; j < 4; j++) bv[j] = Bs[kk][tx * 4 + j];
            #pragma unroll
            for (int i = 0; i < 4; i++)
                #pragma unroll
                for (int j = 0; j < 4; j++)
                    acc[i][j] += av[i] * bv[j];
        }
        __syncthreads();
    }
    #pragma unroll
    for (int i = 0; i < 4; i++) {
        float4 v = make_float4(acc[i][0], acc[i][1], acc[i][2], acc[i][3]);
        *(float4*)&g_h[(m0 + ty * 4 + i) * 512 + n0 + tx * 4] = v;
    }
}

// ---------------- K3: f1/f2 per (row, head) ----------------
__global__ void k_f12(const float* __restrict__ a) {
    int w    = blockIdx.x * 4 + (threadIdx.x >> 5);
    int row  = w >> 2;
    int head = w & 3;
    int lane = threadIdx.x & 31;
    const float* hp = g_h + row * 512 + head * 128;
    const float* ap = a + head * 256;
    float s1 = 0.f, s2 = 0.f;
    #pragma unroll
    for (int c = 0; c < 4; c++) {
        float hv = hp[lane + 32 * c];
        s1 += hv * ap[lane + 32 * c];
        s2 += hv * ap[128 + lane + 32 * c];
    }
    #pragma unroll
    for (int o = 16; o; o >>= 1) {
        s1 += __shfl_xor_sync(0xffffffffu, s1, o);
        s2 += __shfl_xor_sync(0xffffffffu, s2, o);
    }
    if (lane == 0) {
        g_f1[head * N_NODES + row] = s1;
        g_f2[head * N_NODES + row] = s2;
    }
}

// ---------------- K4: layer-1 sparse attention + elu ----------------
__global__ void k_attn1() {
    int row  = blockIdx.x;
    int head = threadIdx.x >> 5;
    int lane = threadIdx.x & 31;
    int base = row & ~1023;
    int cnt  = g_cnt[row];

    int j = 0;
    float e = -INFINITY;
    if (lane < cnt) {
        j = g_nbr[row * KEDGE + lane];
        float t = g_f1[head * N_NODES + row] + g_f2[head * N_NODES + base + j];
        e = (t > 0.f) ? t : ALPHA_LRELU * t;
    }
    float m = e;
    #pragma unroll
    for (int o = 16; o; o >>= 1) m = fmaxf(m, __shfl_xor_sync(0xffffffffu, m, o));
    float p = (lane < cnt) ? __expf(e - m) : 0.f;
    float s = p;
    #pragma unroll
    for (int o = 16; o; o >>= 1) s += __shfl_xor_sync(0xffffffffu, s, o);
    float wgt = p / s;

    float4 acc = make_float4(0.f, 0.f, 0.f, 0.f);
    for (int k = 0; k < cnt; k++) {
        float wk = __shfl_sync(0xffffffffu, wgt, k);
        int   jk = __shfl_sync(0xffffffffu, j, k);
        float4 hv = *(const float4*)&g_h[(base + jk) * 512 + head * 128 + lane * 4];
        acc.x += wk * hv.x; acc.y += wk * hv.y;
        acc.z += wk * hv.z; acc.w += wk * hv.w;
    }
    float4 o4;
    o4.x = acc.x > 0.f ? acc.x : expm1f(acc.x);
    o4.y = acc.y > 0.f ? acc.y : expm1f(acc.y);
    o4.z = acc.z > 0.f ? acc.z : expm1f(acc.z);
    o4.w = acc.w > 0.f ? acc.w : expm1f(acc.w);
    *(float4*)&g_xc[row * 512 + head * 128 + lane * 4] = o4;
}

// ---------------- K5: h2 = xc @ W_out, register-tiled (1 row x 4 classes) ----
// grid 256, block 128. All float4 loads, no smem, no syncs. Fused f1o/f2o.
__global__ void k_gemm2(const float* __restrict__ W, const float* __restrict__ a_out) {
    int t    = blockIdx.x * 128 + threadIdx.x;   // 32768 threads
    int c4   = t & 7;                            // class group (4 classes)
    int row  = t >> 3;
    const float4* xp = (const float4*)(g_xc + (size_t)row * 512);
    const float4* wp = (const float4*)(W + c4 * 4);   // stride 8 float4 per k

    float4 acc = make_float4(0.f, 0.f, 0.f, 0.f);
    #pragma unroll 8
    for (int q = 0; q < 128; q++) {              // q = k/4
        float4 xv = xp[q];
        float4 w0 = wp[(q * 4 + 0) * 8];
        float4 w1 = wp[(q * 4 + 1) * 8];
        float4 w2 = wp[(q * 4 + 2) * 8];
        float4 w3 = wp[(q * 4 + 3) * 8];
        acc.x += xv.x * w0.x + xv.y * w1.x + xv.z * w2.x + xv.w * w3.x;
        acc.y += xv.x * w0.y + xv.y * w1.y + xv.z * w2.y + xv.w * w3.y;
        acc.z += xv.x * w0.z + xv.y * w1.z + xv.z * w2.z + xv.w * w3.z;
        acc.w += xv.x * w0.w + xv.y * w1.w + xv.z * w2.w + xv.w * w3.w;
    }
    *(float4*)&g_h2[row * 32 + c4 * 4] = acc;

    // fused f1o/f2o: reduce partial dots across the 8 lanes sharing this row
    float4 a1 = *(const float4*)&a_out[c4 * 4];
    float4 a2 = *(const float4*)&a_out[32 + c4 * 4];
    float s1 = acc.x * a1.x + acc.y * a1.y + acc.z * a1.z + acc.w * a1.w;
    float s2 = acc.x * a2.x + acc.y * a2.y + acc.z * a2.z + acc.w * a2.w;
    #pragma unroll
    for (int o = 4; o; o >>= 1) {
        s1 += __shfl_xor_sync(0xffffffffu, s1, o);
        s2 += __shfl_xor_sync(0xffffffffu, s2, o);
    }
    if (c4 == 0) { g_f1o[row] = s1; g_f2o[row] = s2; }
}

// ---------------- K6: layer-2 attention + elu + log_softmax ----------------
__global__ void k_attn2(float* __restrict__ out) {
    int row  = blockIdx.x * 4 + (threadIdx.x >> 5);
    int lane = threadIdx.x & 31;
    int base = row & ~1023;
    int cnt  = g_cnt[row];

    int j = 0;
    float e = -INFINITY;
    if (lane < cnt) {
        j = g_nbr[row * KEDGE + lane];
        float t = g_f1o[row] + g_f2o[base + j];
        e = (t > 0.f) ? t : ALPHA_LRELU * t;
    }
    float m = e;
    #pragma unroll
    for (int o = 16; o; o >>= 1) m = fmaxf(m, __shfl_xor_sync(0xffffffffu, m, o));
    float p = (lane < cnt) ? __expf(e - m) : 0.f;
    float s = p;
    #pragma unroll
    for (int o = 16; o; o >>= 1) s += __shfl_xor_sync(0xffffffffu, s, o);
    float wgt = p / s;

    float acc = 0.f;
    for (int k = 0; k < cnt; k++) {
        float wk = __shfl_sync(0xffffffffu, wgt, k);
        int   jk = __shfl_sync(0xffffffffu, j, k);
        acc += wk * g_h2[(base + jk) * 32 + lane];
    }
    float v = acc > 0.f ? acc : expm1f(acc);
    // log_softmax over the 32 lanes
    float m2 = v;
    #pragma unroll
    for (int o = 16; o; o >>= 1) m2 = fmaxf(m2, __shfl_xor_sync(0xffffffffu, m2, o));
    float se = __expf(v - m2);
    #pragma unroll
    for (int o = 16; o; o >>= 1) se += __shfl_xor_sync(0xffffffffu, se, o);
    out[row * 32 + lane] = v - m2 - logf(se);
}

// ---------------- launch ----------------
extern "C" void kernel_launch(void* const* d_in, const int* in_sizes, int n_in,
                              void* d_out, int out_size) {
    const float* x     = (const float*)d_in[0];
    const int*   edge  = (const int*)d_in[1];
    // d_in[2] = node_num (1024, fixed)
    const float* Ws    = (const float*)d_in[3];
    const float* a     = (const float*)d_in[4];
    const float* W_out = (const float*)d_in[5];
    const float* a_out = (const float*)d_in[6];
    float* out = (float*)d_out;

    k_nbrs<<<N_NODES / 4, 128>>>(edge);
    dim3 g1(8, 64);
    k_gemm1<<<g1, 256>>>(x, Ws);
    k_f12<<<N_NODES, 128>>>(a);
    k_attn1<<<N_NODES, 128>>>();
    k_gemm2<<<256, 128>>>(W_out, a_out);
    k_attn2<<<N_NODES / 4, 128>>>(out);
}

// round 8
// speedup vs baseline: 1.2030x; 1.1340x over previous
#include <cuda_runtime.h>
#include <math.h>

#define N_NODES 4096
#define NFEAT   128
#define NHID    128
#define NHEADS  4
#define NCLASS  32
#define KEDGE   32
#define ALPHA_LRELU 0.2f

// ---------------- scratch (no allocations allowed) ----------------
__device__ float g_h  [N_NODES * NHEADS * NHID];   // [n][head*128+d]
__device__ float g_xc [N_NODES * NHEADS * NHID];   // [n][head*128+d]
__device__ float g_f1 [NHEADS * N_NODES];
__device__ float g_f2 [NHEADS * N_NODES];
__device__ float g_h2 [N_NODES * NCLASS];
__device__ float g_f1o[N_NODES];
__device__ float g_f2o[N_NODES];
__device__ int   g_cnt[N_NODES];
__device__ int   g_nbr[N_NODES * KEDGE];
__device__ float4 g_wt[4096];   // wt2[q][lane]: {W[4q][l],W[4q+1][l],W[4q+2][l],W[4q+3][l]}

// ---------------- K0: transpose W_out into interleaved float4 form ----------------
__global__ void k_wt(const float* __restrict__ W) {
    int idx  = blockIdx.x * 256 + threadIdx.x;   // 0..4095
    int q    = idx >> 5;
    int lane = idx & 31;
    float4 v;
    v.x = W[(4 * q + 0) * 32 + lane];
    v.y = W[(4 * q + 1) * 32 + lane];
    v.z = W[(4 * q + 2) * 32 + lane];
    v.w = W[(4 * q + 3) * 32 + lane];
    g_wt[idx] = v;
}

// ---------------- K1: dedup neighbor lists ----------------
__global__ void k_nbrs(const int* __restrict__ edge) {
    int row  = blockIdx.x * 4 + (threadIdx.x >> 5);
    int lane = threadIdx.x & 31;
    int e = edge[row * KEDGE + lane];
    bool valid = (e >= 0);
    unsigned key = valid ? (unsigned)e : (0x40000000u + (unsigned)lane);
    unsigned grp = __match_any_sync(0xffffffffu, key);
    bool uniq = valid && ((__ffs(grp) - 1) == lane);
    unsigned bal = __ballot_sync(0xffffffffu, uniq);
    if (uniq) {
        int pos = __popc(bal & ((1u << lane) - 1u));
        g_nbr[row * KEDGE + pos] = e;
    }
    if (lane == 0) g_cnt[row] = __popc(bal);
}

// ---------------- K2: h = x @ concat(Ws) ----------------
__global__ void k_gemm1(const float* __restrict__ X, const float* __restrict__ Ws) {
    __shared__ __align__(16) float As[64][68];  // [k][m], pad 68 -> LDS.128
    __shared__ __align__(16) float Bs[64][68];  // [k][n]
    int bx = blockIdx.x;
    int by = blockIdx.y;
    int n0 = bx * 64;
    int head = n0 >> 7;
    int nloc = n0 & 127;
    const float* B = Ws + head * NFEAT * NHID;
    int m0 = by * 64;
    int tid = threadIdx.x;
    int tx = tid & 15, ty = tid >> 4;

    float acc[4][4] = {};
    for (int kc = 0; kc < NFEAT; kc += 64) {
        #pragma unroll
        for (int t = 0; t < 16; t++) {
            int e = t * 256 + tid;
            { int k = e & 63, m = e >> 6;
              As[k][m] = X[(m0 + m) * NFEAT + kc + k]; }
            { int n = e & 63, k = e >> 6;
              Bs[k][n] = B[(kc + k) * NHID + nloc + n]; }
        }
        __syncthreads();
        #pragma unroll 16
        for (int kk = 0; kk < 64; kk++) {
            float4 av4 = *(const float4*)&As[kk][ty * 4];
            float4 bv4 = *(const float4*)&Bs[kk][tx * 4];
            float av[4] = {av4.x, av4.y, av4.z, av4.w};
            float bv[4] = {bv4.x, bv4.y, bv4.z, bv4.w};
            #pragma unroll
            for (int i = 0; i < 4; i++)
                #pragma unroll
                for (int j = 0; j < 4; j++)
                    acc[i][j] += av[i] * bv[j];
        }
        __syncthreads();
    }
    #pragma unroll
    for (int i = 0; i < 4; i++) {
        float4 v = make_float4(acc[i][0], acc[i][1], acc[i][2], acc[i][3]);
        *(float4*)&g_h[(m0 + ty * 4 + i) * 512 + n0 + tx * 4] = v;
    }
}

// ---------------- K3: f1/f2 per (row, head) ----------------
__global__ void k_f12(const float* __restrict__ a) {
    int w    = blockIdx.x * 4 + (threadIdx.x >> 5);
    int row  = w >> 2;
    int head = w & 3;
    int lane = threadIdx.x & 31;
    const float* hp = g_h + row * 512 + head * 128;
    const float* ap = a + head * 256;
    float s1 = 0.f, s2 = 0.f;
    #pragma unroll
    for (int c = 0; c < 4; c++) {
        float hv = hp[lane + 32 * c];
        s1 += hv * ap[lane + 32 * c];
        s2 += hv * ap[128 + lane + 32 * c];
    }
    #pragma unroll
    for (int o = 16; o; o >>= 1) {
        s1 += __shfl_xor_sync(0xffffffffu, s1, o);
        s2 += __shfl_xor_sync(0xffffffffu, s2, o);
    }
    if (lane == 0) {
        g_f1[head * N_NODES + row] = s1;
        g_f2[head * N_NODES + row] = s2;
    }
}

// ---------------- K4: layer-1 sparse attention + elu ----------------
__global__ void k_attn1() {
    int row  = blockIdx.x;
    int head = threadIdx.x >> 5;
    int lane = threadIdx.x & 31;
    int base = row & ~1023;
    int cnt  = g_cnt[row];

    int j = 0;
    float e = -INFINITY;
    if (lane < cnt) {
        j = g_nbr[row * KEDGE + lane];
        float t = g_f1[head * N_NODES + row] + g_f2[head * N_NODES + base + j];
        e = (t > 0.f) ? t : ALPHA_LRELU * t;
    }
    float m = e;
    #pragma unroll
    for (int o = 16; o; o >>= 1) m = fmaxf(m, __shfl_xor_sync(0xffffffffu, m, o));
    float p = (lane < cnt) ? __expf(e - m) : 0.f;
    float s = p;
    #pragma unroll
    for (int o = 16; o; o >>= 1) s += __shfl_xor_sync(0xffffffffu, s, o);
    float wgt = p / s;

    float4 acc = make_float4(0.f, 0.f, 0.f, 0.f);
    for (int k = 0; k < cnt; k++) {
        float wk = __shfl_sync(0xffffffffu, wgt, k);
        int   jk = __shfl_sync(0xffffffffu, j, k);
        float4 hv = *(const float4*)&g_h[(base + jk) * 512 + head * 128 + lane * 4];
        acc.x += wk * hv.x; acc.y += wk * hv.y;
        acc.z += wk * hv.z; acc.w += wk * hv.w;
    }
    float4 o4;
    o4.x = acc.x > 0.f ? acc.x : expm1f(acc.x);
    o4.y = acc.y > 0.f ? acc.y : expm1f(acc.y);
    o4.z = acc.z > 0.f ? acc.z : expm1f(acc.z);
    o4.w = acc.w > 0.f ? acc.w : expm1f(acc.w);
    *(float4*)&g_xc[row * 512 + head * 128 + lane * 4] = o4;
}

// ---------------- K5: h2 = xc @ W_out — warp=row, lane=class, wt2 float4 ----
// grid 512, block 256 (8 warps). Per q: 1 uniform x-LDG.128 + 1 coalesced wt-LDG.128.
__global__ void k_gemm2(const float* __restrict__ a_out) {
    int lane = threadIdx.x & 31;
    int warp = threadIdx.x >> 5;
    int row  = blockIdx.x * 8 + warp;
    const float4* xp = (const float4*)(g_xc + (size_t)row * 512);
    const float4* wp = g_wt + lane;

    float ax = 0.f, ay = 0.f, az = 0.f, aw = 0.f;
    #pragma unroll 4
    for (int q = 0; q < 128; q++) {
        float4 xv = xp[q];            // uniform across warp (1 line)
        float4 wv = wp[q * 32];       // coalesced 512B (L1-hot)
        ax += xv.x * wv.x;
        ay += xv.y * wv.y;
        az += xv.z * wv.z;
        aw += xv.w * wv.w;
    }
    float acc = (ax + ay) + (az + aw);
    g_h2[row * 32 + lane] = acc;

    float s1 = acc * a_out[lane];
    float s2 = acc * a_out[32 + lane];
    #pragma unroll
    for (int o = 16; o; o >>= 1) {
        s1 += __shfl_xor_sync(0xffffffffu, s1, o);
        s2 += __shfl_xor_sync(0xffffffffu, s2, o);
    }
    if (lane == 0) { g_f1o[row] = s1; g_f2o[row] = s2; }
}

// ---------------- K6: layer-2 attention + elu + log_softmax ----------------
__global__ void k_attn2(float* __restrict__ out) {
    int row  = blockIdx.x * 4 + (threadIdx.x >> 5);
    int lane = threadIdx.x & 31;
    int base = row & ~1023;
    int cnt  = g_cnt[row];

    int j = 0;
    float e = -INFINITY;
    if (lane < cnt) {
        j = g_nbr[row * KEDGE + lane];
        float t = g_f1o[row] + g_f2o[base + j];
        e = (t > 0.f) ? t : ALPHA_LRELU * t;
    }
    float m = e;
    #pragma unroll
    for (int o = 16; o; o >>= 1) m = fmaxf(m, __shfl_xor_sync(0xffffffffu, m, o));
    float p = (lane < cnt) ? __expf(e - m) : 0.f;
    float s = p;
    #pragma unroll
    for (int o = 16; o; o >>= 1) s += __shfl_xor_sync(0xffffffffu, s, o);
    float wgt = p / s;

    float acc = 0.f;
    for (int k = 0; k < cnt; k++) {
        float wk = __shfl_sync(0xffffffffu, wgt, k);
        int   jk = __shfl_sync(0xffffffffu, j, k);
        acc += wk * g_h2[(base + jk) * 32 + lane];
    }
    float v = acc > 0.f ? acc : expm1f(acc);
    float m2 = v;
    #pragma unroll
    for (int o = 16; o; o >>= 1) m2 = fmaxf(m2, __shfl_xor_sync(0xffffffffu, m2, o));
    float se = __expf(v - m2);
    #pragma unroll
    for (int o = 16; o; o >>= 1) se += __shfl_xor_sync(0xffffffffu, se, o);
    out[row * 32 + lane] = v - m2 - logf(se);
}

// ---------------- launch ----------------
extern "C" void kernel_launch(void* const* d_in, const int* in_sizes, int n_in,
                              void* d_out, int out_size) {
    const float* x     = (const float*)d_in[0];
    const int*   edge  = (const int*)d_in[1];
    const float* Ws    = (const float*)d_in[3];
    const float* a     = (const float*)d_in[4];
    const float* W_out = (const float*)d_in[5];
    const float* a_out = (const float*)d_in[6];
    float* out = (float*)d_out;

    k_wt<<<16, 256>>>(W_out);
    k_nbrs<<<N_NODES / 4, 128>>>(edge);
    dim3 g1(8, 64);
    k_gemm1<<<g1, 256>>>(x, Ws);
    k_f12<<<N_NODES, 128>>>(a);
    k_attn1<<<N_NODES, 128>>>();
    k_gemm2<<<512, 256>>>(a_out);
    k_attn2<<<N_NODES / 4, 128>>>(out);
}